// round 6
// baseline (speedup 1.0000x reference)
#include <cuda_runtime.h>
#include <cuda_bf16.h>

#define NTHR 256
// smem strides (float2 units) for the 4 mode axes
#define S0 585
#define S1 73
#define S2 9
#define ST_SIZE 4680       // state floats2
#define ENC_OFF ST_SIZE    // enc scratch after state (float2 units)
#define SMEM_F2 (ST_SIZE + 400)

typedef unsigned long long u64t;

// ---------------------------------------------------------------------------
// Packed gates: every complex entry u stored as float4 (ur, ui, -ui, ur) so
// one LDG.128 provides both f32x2 multiplicands for the packed complex MAC:
//   acc += s.re*(ur,ui) + s.im*(-ui,ur)  ==  acc += u*s   (2 x fma.rn.f32x2)
// BS entries block-major by total photon number n, row-major in block.
// ---------------------------------------------------------------------------
__device__ __align__(16) float4 g_bs4[48][344];
__device__ __align__(16) float4 g_sq4[16][64];
__device__ __align__(16) float4 g_dp4[16][64];

__constant__ int OFF4c[15] = {0,1,5,14,30,55,91,140,204,253,289,314,330,339,343};
__constant__ int c_PI[6] = {0,0,0,1,1,2};
__constant__ int c_PJ[6] = {1,2,3,2,3,3};
__constant__ int c_SA[6] = {585,585,585,73,73,9};
__constant__ int c_SB[6] = {73,9,1,9,1,1};
__constant__ int c_Q0[6] = {9,73,73,585,585,585};
__constant__ int c_Q1[6] = {1,1,9,1,9,73};
__constant__ int c_SM[4] = {585,73,9,1};
__constant__ int c_O0[4] = {73,585,585,585};
__constant__ int c_O1[4] = {9,9,73,73};
__constant__ int c_O2[4] = {1,1,1,9};

__device__ __forceinline__ float2 cmul(float2 a, float2 b) {
    return make_float2(fmaf(a.x, b.x, -a.y * b.y), fmaf(a.x, b.y, a.y * b.x));
}
__device__ __forceinline__ u64t bcast2(float v) {
    u64t r; asm("mov.b64 %0, {%1, %1};" : "=l"(r) : "f"(v)); return r;
}
__device__ __forceinline__ void ffma2(u64t& d, u64t a, u64t b) {
    asm("fma.rn.f32x2 %0, %1, %2, %0;" : "+l"(d) : "l"(a), "l"(b));
}

// ===========================================================================
// Precompute: 80 blocks. expm via Taylor-Horner (sparse gen) + squaring.
//  0..47  beamsplitter (64x64) -> phase-folded, block-packed float4
//  48..63 squeeze 8x8    (l*4+w) -> pending phases folded
//  64..79 displacement 8x8
// ===========================================================================
__global__ __launch_bounds__(NTHR) void precompute_kernel(
    const float* __restrict__ th1, const float* __restrict__ ph1,
    const float* __restrict__ th2, const float* __restrict__ ph2,
    const float* __restrict__ dr,  const float* __restrict__ dphi,
    const float* __restrict__ sr,  const float* __restrict__ sphi,
    const float* __restrict__ kerr)
{
    __shared__ float2 T[4096 + 128];
    int bid = blockIdx.x, t = threadIdx.x;

    if (bid < 48) {
        int l = bid / 12, rem = bid % 12, intf = rem / 6, p = rem % 6;
        int i = c_PI[p], j = c_PJ[p];
        const float* th = intf ? th2 : th1;
        const float* PH = (intf ? ph2 : ph1) + l * 16;
        float theta = th[l*16 + i*4 + j];
        float phiv  = PH[i*4 + j];
        float cp, sp; sincosf(phiv, &sp, &cp);
        const float scale = 1.0f / 256.0f;   // 8 squarings

        for (int e = t; e < 4096; e += NTHR) {
            int r = e >> 6, c = e & 63;
            T[e] = make_float2((r == c) ? 1.f : 0.f, 0.f);
        }
        __syncthreads();

        for (int k = 10; k >= 1; k--) {
            float invk = 1.0f / (float)k;
            float2 Cn[16];
            #pragma unroll
            for (int q = 0; q < 16; q++) {
                int e = t * 16 + q;
                int r = e >> 6, c = e & 63;
                int a = r >> 3, b = r & 7;
                float2 acc = make_float2(0.f, 0.f);
                if (a < 7 && b > 0) {
                    float coef = theta * sqrtf((float)((a + 1) * b)) * scale;
                    float2 co = make_float2(coef * cp, coef * sp);
                    float2 pr = cmul(co, T[((a + 1) * 8 + (b - 1)) * 64 + c]);
                    acc.x += pr.x; acc.y += pr.y;
                }
                if (a > 0 && b < 7) {
                    float coef = theta * sqrtf((float)(a * (b + 1))) * scale;
                    float2 co = make_float2(-coef * cp, coef * sp);
                    float2 pr = cmul(co, T[((a - 1) * 8 + (b + 1)) * 64 + c]);
                    acc.x += pr.x; acc.y += pr.y;
                }
                acc.x *= invk; acc.y *= invk;
                if (r == c) acc.x += 1.0f;
                Cn[q] = acc;
            }
            __syncthreads();
            #pragma unroll
            for (int q = 0; q < 16; q++) T[t * 16 + q] = Cn[q];
            __syncthreads();
        }
        for (int sq = 0; sq < 8; sq++) {
            float2 Cn[16];
            #pragma unroll
            for (int q = 0; q < 16; q++) {
                int e = t * 16 + q;
                int r = e >> 6, c = e & 63;
                float2 acc = make_float2(0.f, 0.f);
                for (int m = 0; m < 64; m++) {
                    float2 av = T[r * 64 + m];
                    float2 bv = T[m * 64 + c];
                    acc.x = fmaf(av.x, bv.x, acc.x); acc.x = fmaf(-av.y, bv.y, acc.x);
                    acc.y = fmaf(av.x, bv.y, acc.y); acc.y = fmaf(av.y, bv.x, acc.y);
                }
                Cn[q] = acc;
            }
            __syncthreads();
            #pragma unroll
            for (int q = 0; q < 16; q++) T[t * 16 + q] = Cn[q];
            __syncthreads();
        }

        // pending-phase (alpha*n + beta*n^2) fold, then pack block-major
        float a4[4] = {PH[0], PH[5], PH[10], PH[15]};
        float b4[4] = {0.f, 0.f, 0.f, 0.f};
        if (intf == 0 && l > 0) {
            b4[0] = kerr[(l-1)*4+0]; b4[1] = kerr[(l-1)*4+1];
            b4[2] = kerr[(l-1)*4+2]; b4[3] = kerr[(l-1)*4+3];
        }
        for (int pp = 0; pp < p; pp++) {
            int ii = c_PI[pp], jj = c_PJ[pp];
            a4[ii] = 0.f; b4[ii] = 0.f;
            a4[jj] = PH[jj*4 + ii]; b4[jj] = 0.f;
        }
        float Ai = a4[i], Bi = b4[i], Aj = a4[j], Bj = b4[j];

        for (int e2 = t; e2 < 344; e2 += NTHR) {
            int n = 0;
            #pragma unroll
            for (int m = 1; m < 15; m++) if (e2 >= OFF4c[m]) n = m;
            int K = 8 - ((n < 7) ? (7 - n) : (n - 7));
            int lo = (n > 7) ? (n - 7) : 0;
            int loc = e2 - OFF4c[n];
            int aidx = loc / K, cidx = loc % K;
            int a = lo + aidx, b = n - a, c = lo + cidx, d = n - c;
            float2 v = T[(a * 8 + b) * 64 + (c * 8 + d)];
            float P = Ai * (float)c + Bi * (float)(c * c)
                    + Aj * (float)d + Bj * (float)(d * d);
            float sn, cn; sincosf(P, &sn, &cn);
            v = cmul(v, make_float2(cn, sn));
            g_bs4[bid][e2] = make_float4(v.x, v.y, -v.y, v.x);
        }
    } else {
        int idx = bid - 48;
        bool is_sq = (idx < 16);
        int li = is_sq ? idx : (idx - 16);
        int l2 = li >> 2, w = li & 3;
        float2* Tsm = T;
        float2* Hsm = T + 64;
        int r = t >> 3, c = t & 7;

        if (t < 64) {
            float2 h = make_float2(0.f, 0.f);
            if (is_sq) {
                float rv = sr[li], pv = sphi[li];
                float cps, sps; sincosf(pv, &sps, &cps);
                float zr = rv * cps, zi = rv * sps;
                if (c == r + 2) {
                    float f = sqrtf((float)((r + 1) * (r + 2)));
                    h.x += 0.5f * zr * f;  h.y += -0.5f * zi * f;
                }
                if (c + 2 == r) {
                    float f = sqrtf((float)((c + 1) * (c + 2)));
                    h.x += -0.5f * zr * f; h.y += -0.5f * zi * f;
                }
            } else {
                float rv = dr[li], pv = dphi[li];
                float mm = rv * cosf(pv);
                float thp = rv * sinf(pv);
                float cth, sth; sincosf(thp, &sth, &cth);
                float ax = mm * cth, ay = mm * sth;
                if (c + 1 == r) {
                    float f = sqrtf((float)r);
                    h.x += ax * f; h.y += ay * f;
                }
                if (c == r + 1) {
                    float f = sqrtf((float)(r + 1));
                    h.x += -ax * f; h.y += ay * f;
                }
            }
            const float sc16 = 1.0f / 16.0f;  // 4 squarings
            h.x *= sc16; h.y *= sc16;
            Hsm[t] = h;
            Tsm[t] = make_float2((r == c) ? 1.f : 0.f, 0.f);
        }
        __syncthreads();

        for (int k = 10; k >= 1; k--) {
            float2 v = make_float2(0.f, 0.f);
            if (t < 64) {
                #pragma unroll
                for (int m = 0; m < 8; m++) {
                    float2 hm = Hsm[r * 8 + m];
                    float2 tm = Tsm[m * 8 + c];
                    v.x = fmaf(hm.x, tm.x, v.x); v.x = fmaf(-hm.y, tm.y, v.x);
                    v.y = fmaf(hm.x, tm.y, v.y); v.y = fmaf(hm.y, tm.x, v.y);
                }
                float ik = 1.0f / (float)k;
                v.x *= ik; v.y *= ik;
                if (r == c) v.x += 1.0f;
            }
            __syncthreads();
            if (t < 64) Tsm[t] = v;
            __syncthreads();
        }
        for (int sq = 0; sq < 4; sq++) {
            float2 v = make_float2(0.f, 0.f);
            if (t < 64) {
                #pragma unroll
                for (int m = 0; m < 8; m++) {
                    float2 av = Tsm[r * 8 + m];
                    float2 bv = Tsm[m * 8 + c];
                    v.x = fmaf(av.x, bv.x, v.x); v.x = fmaf(-av.y, bv.y, v.x);
                    v.y = fmaf(av.x, bv.y, v.y); v.y = fmaf(av.y, bv.x, v.y);
                }
            }
            __syncthreads();
            if (t < 64) Tsm[t] = v;
            __syncthreads();
        }
        if (t < 64) {
            const float* PH = (is_sq ? ph1 : ph2) + l2 * 16;
            float a4[4] = {PH[0], PH[5], PH[10], PH[15]};
            float b4[4] = {0.f, 0.f, 0.f, 0.f};
            if (is_sq && l2 > 0) {
                b4[0] = kerr[(l2-1)*4+0]; b4[1] = kerr[(l2-1)*4+1];
                b4[2] = kerr[(l2-1)*4+2]; b4[3] = kerr[(l2-1)*4+3];
            }
            for (int pp = 0; pp < 6; pp++) {
                int ii = c_PI[pp], jj = c_PJ[pp];
                a4[ii] = 0.f; b4[ii] = 0.f;
                a4[jj] = PH[jj*4 + ii]; b4[jj] = 0.f;
            }
            float P = a4[w] * (float)c + b4[w] * (float)(c * c);
            float sn, cn; sincosf(P, &sn, &cn);
            float2 v = cmul(Tsm[t], make_float2(cn, sn));
            float4 pk = make_float4(v.x, v.y, -v.y, v.x);
            if (is_sq) g_sq4[li][t] = pk;
            else       g_dp4[li][t] = pk;
        }
    }
}

// ===========================================================================
// Main kernel pieces
// ===========================================================================

// One (block, fiber) task: K x K complex GEMV in place, packed f32x2 MACs.
template<int K, int N, int OFF>
__device__ __forceinline__ void bs_unit(float2* st, const float4* __restrict__ U,
                                        int fb, int SA, int SB)
{
    constexpr int LO = (N > 7) ? (N - 7) : 0;
    int base = fb + LO * SA + (N - LO) * SB;
    int dS = SA - SB;
    u64t sr[K], si[K];
    #pragma unroll
    for (int c = 0; c < K; c++) {
        float2 s = st[base + c * dS];
        sr[c] = bcast2(s.x); si[c] = bcast2(s.y);
    }
    #pragma unroll
    for (int a = 0; a < K; a++) {
        u64t acc = 0ULL;
        #pragma unroll
        for (int c = 0; c < K; c++) {
            ulonglong2 uu = __ldg((const ulonglong2*)&U[OFF + a * K + c]);
            ffma2(acc, sr[c], uu.x);
            ffma2(acc, si[c], uu.y);
        }
        *(u64t*)&st[base + a * dS] = acc;   // inputs already cached in regs
    }
}

// Single-mode 8x8 gate, in place; 2 fibers per thread sharing matrix LDG.
__device__ __noinline__ void apply1g(float2* st, const float4* __restrict__ U,
                                     int SM, int O0, int O1, int O2, int t)
{
    int a = t >> 5, b2 = (t >> 2) & 7, cp = (t & 3) * 2;
    int base1 = a * O0 + b2 * O1 + cp * O2;
    int base2 = base1 + O2;
    u64t acc[16];
    #pragma unroll
    for (int o = 0; o < 16; o++) acc[o] = 0ULL;
    #pragma unroll
    for (int c = 0; c < 8; c++) {
        float2 s1 = st[base1 + c * SM];
        float2 s2 = st[base2 + c * SM];
        u64t s1r = bcast2(s1.x), s1i = bcast2(s1.y);
        u64t s2r = bcast2(s2.x), s2i = bcast2(s2.y);
        #pragma unroll
        for (int o = 0; o < 8; o++) {
            ulonglong2 uu = __ldg((const ulonglong2*)&U[o * 8 + c]);
            ffma2(acc[o],     s1r, uu.x); ffma2(acc[o],     s1i, uu.y);
            ffma2(acc[o + 8], s2r, uu.x); ffma2(acc[o + 8], s2i, uu.y);
        }
    }
    #pragma unroll
    for (int o = 0; o < 8; o++) {
        *(u64t*)&st[base1 + o * SM] = acc[o];
        *(u64t*)&st[base2 + o * SM] = acc[o + 8];
    }
}

// ===========================================================================
// Main kernel: one CTA per batch element, in-place state, 1 barrier/gate.
// ===========================================================================
__global__ __launch_bounds__(NTHR, 3) void qnn_main(
    const float* __restrict__ x, float* __restrict__ out)
{
    extern __shared__ float2 sm[];
    float2* st = sm;
    float* enc = (float*)(sm + ENC_OFF);       // encH/A/B 3*256 + red 32
    float* encH = enc, *encA = enc + 256, *encB = enc + 512;
    float* red = enc + 768;

    int b = blockIdx.x, t = threadIdx.x;
    int wid = t >> 5, lane = t & 31;

    // ---- per-sample encoding expm: E_g = expm(x_g (AD - A)), real 8x8 ----
    {
        int g = t >> 6, e = t & 63, r = e >> 3, c = e & 7;
        float xv = __ldg(&x[b * 4 + g]);
        float sc = xv * (1.0f / 64.0f);   // 6 squarings
        float h = 0.f;
        if (c == r - 1) h = sc * sqrtf((float)r);
        else if (c == r + 1) h = -sc * sqrtf((float)(r + 1));
        encH[g * 64 + e] = h;
        encA[g * 64 + e] = (r == c) ? 1.f : 0.f;
        __syncthreads();

        float* Ta = encA + g * 64;
        float* Tb = encB + g * 64;
        for (int k = 9; k >= 1; k--) {
            float acc = 0.f;
            #pragma unroll
            for (int m = 0; m < 8; m++)
                acc = fmaf(encH[g * 64 + r * 8 + m], Ta[m * 8 + c], acc);
            float v = acc / (float)k + ((r == c) ? 1.f : 0.f);
            Tb[e] = v;
            __syncthreads();
            float* tmp = Ta; Ta = Tb; Tb = tmp;
        }
        for (int sq = 0; sq < 6; sq++) {
            float acc = 0.f;
            #pragma unroll
            for (int m = 0; m < 8; m++) acc = fmaf(Ta[r * 8 + m], Ta[m * 8 + c], acc);
            Tb[e] = acc;
            __syncthreads();
            float* tmp = Ta; Ta = Tb; Tb = tmp;
        }
        // 15 swaps from encA -> final matrix lives in encB region
    }

    // ---- init state: outer product of E_g column 0 (vacuum input) ----
    #pragma unroll 1
    for (int q = 0; q < 16; q++) {
        int e = t * 16 + q;
        int i = e >> 9, j = (e >> 6) & 7, k = (e >> 3) & 7, l2 = e & 7;
        float v = encB[0 * 64 + i * 8] * encB[1 * 64 + j * 8]
                * encB[2 * 64 + k * 8] * encB[3 * 64 + l2 * 8];
        st[i * S0 + j * S1 + k * S2 + l2] = make_float2(v, 0.f);
    }
    __syncthreads();

    // ---- circuit ----
    int fiber = (wid & 1) * 32 + lane;          // fiber-half per warp parity
    int shi = fiber >> 3, slo = fiber & 7;
    int wg = wid >> 1;                          // 4 schedule groups

    #pragma unroll 1
    for (int l = 0; l < 4; l++) {
        #pragma unroll 1
        for (int hh = 0; hh < 2; hh++) {
            #pragma unroll 1
            for (int p = 0; p < 6; p++) {
                const float4* U = g_bs4[l * 12 + hh * 6 + p];
                int SA = c_SA[p], SB = c_SB[p];
                int fb = shi * c_Q0[p] + slo * c_Q1[p];
                if (wg == 0) {
                    bs_unit<8, 7, 140>(st, U, fb, SA, SB);
                    bs_unit<4, 3,  14>(st, U, fb, SA, SB);
                    bs_unit<2, 1,   1>(st, U, fb, SA, SB);
                    bs_unit<1, 0,   0>(st, U, fb, SA, SB);
                } else if (wg == 1) {
                    bs_unit<7, 6,  91>(st, U, fb, SA, SB);
                    bs_unit<6, 5,  55>(st, U, fb, SA, SB);
                    bs_unit<1, 14, 343>(st, U, fb, SA, SB);
                } else if (wg == 2) {
                    bs_unit<7, 8, 204>(st, U, fb, SA, SB);
                    bs_unit<6, 9, 253>(st, U, fb, SA, SB);
                } else {
                    bs_unit<5, 4,  30>(st, U, fb, SA, SB);
                    bs_unit<5, 10, 289>(st, U, fb, SA, SB);
                    bs_unit<4, 11, 314>(st, U, fb, SA, SB);
                    bs_unit<3, 2,   5>(st, U, fb, SA, SB);
                    bs_unit<3, 12, 330>(st, U, fb, SA, SB);
                    bs_unit<2, 13, 339>(st, U, fb, SA, SB);
                }
                __syncthreads();
            }
            #pragma unroll 1
            for (int w = 0; w < 4; w++) {
                const float4* G = hh ? g_dp4[l * 4 + w] : g_sq4[l * 4 + w];
                apply1g(st, G, c_SM[w], c_O0[w], c_O1[w], c_O2[w], t);
                __syncthreads();
            }
        }
    }

    // ---- expectations <n_w> ----
    float ev0 = 0.f, ev1 = 0.f, ev2 = 0.f, ev3 = 0.f;
    #pragma unroll 1
    for (int q = 0; q < 16; q++) {
        int e = t * 16 + q;
        int i = e >> 9, j = (e >> 6) & 7, k = (e >> 3) & 7, l2 = e & 7;
        float2 a = st[i * S0 + j * S1 + k * S2 + l2];
        float p = a.x * a.x + a.y * a.y;
        ev0 = fmaf(p, (float)i, ev0);
        ev1 = fmaf(p, (float)j, ev1);
        ev2 = fmaf(p, (float)k, ev2);
        ev3 = fmaf(p, (float)l2, ev3);
    }
    #pragma unroll
    for (int off2 = 16; off2; off2 >>= 1) {
        ev0 += __shfl_down_sync(0xFFFFFFFFu, ev0, off2);
        ev1 += __shfl_down_sync(0xFFFFFFFFu, ev1, off2);
        ev2 += __shfl_down_sync(0xFFFFFFFFu, ev2, off2);
        ev3 += __shfl_down_sync(0xFFFFFFFFu, ev3, off2);
    }
    if (lane == 0) {
        red[0 * 8 + wid] = ev0; red[1 * 8 + wid] = ev1;
        red[2 * 8 + wid] = ev2; red[3 * 8 + wid] = ev3;
    }
    __syncthreads();
    if (t < 4) {
        float s = 0.f;
        #pragma unroll
        for (int wv = 0; wv < 8; wv++) s += red[t * 8 + wv];
        out[b * 4 + t] = s;
    }
}

extern "C" void kernel_launch(void* const* d_in, const int* in_sizes, int n_in,
                              void* d_out, int out_size) {
    const float* x    = (const float*)d_in[0];
    const float* th1  = (const float*)d_in[1];
    const float* ph1  = (const float*)d_in[2];
    const float* th2  = (const float*)d_in[3];
    const float* ph2  = (const float*)d_in[4];
    const float* dr   = (const float*)d_in[5];
    const float* dphi = (const float*)d_in[6];
    const float* sr   = (const float*)d_in[7];
    const float* sphi = (const float*)d_in[8];
    const float* kerr = (const float*)d_in[9];
    float* out = (float*)d_out;
    int Bn = in_sizes[0] / 4;

    int smem_bytes = SMEM_F2 * (int)sizeof(float2);
    cudaFuncSetAttribute(qnn_main, cudaFuncAttributeMaxDynamicSharedMemorySize, smem_bytes);

    precompute_kernel<<<80, NTHR>>>(th1, ph1, th2, ph2, dr, dphi, sr, sphi, kerr);
    qnn_main<<<Bn, NTHR, smem_bytes>>>(x, out);
}

// round 7
// speedup vs baseline: 2.4319x; 2.4319x over previous
#include <cuda_runtime.h>
#include <cuda_bf16.h>

#define NTHR 256
// smem strides (float2 units) for the 4 mode axes
#define S0 585
#define S1 73
#define S2 9
#define ST_SIZE 4680       // state (float2)

// ---------------------------------------------------------------------------
// Packed block-diagonal beamsplitter storage (two complex entries per float4).
// Block n (total photon number 0..14): K = 8-|n-7| rows/cols, row padded to
// RK = K+(K&1) float2 so every row is float4-aligned. Layout:
//   g_bs[gate][ OFFP[n] + a_idx*RK + c_idx ]
// ---------------------------------------------------------------------------
__device__ __align__(16) float2 g_bs[48][376];
__device__ __align__(16) float2 g_sq[16][64];   // squeeze  [out*8+in], phases folded
__device__ __align__(16) float2 g_dp[16][64];   // displacement, phases folded

__constant__ int OFFP[16] = {0,2,6,18,34,64,100,156,220,276,312,342,358,370,374,376};
__constant__ int c_PI[6] = {0,0,0,1,1,2};
__constant__ int c_PJ[6] = {1,2,3,2,3,3};
// BS strides per pair p: active modes (i,j) and spectator modes (q0,q1)
__constant__ int c_SA[6] = {585,585,585,73,73,9};
__constant__ int c_SB[6] = {73,9,1,9,1,1};
__constant__ int c_Q0[6] = {9,73,73,585,585,585};
__constant__ int c_Q1[6] = {1,1,9,1,9,73};
// single-mode gate strides
__constant__ int c_SM[4] = {585,73,9,1};
__constant__ int c_O0[4] = {73,585,585,585};
__constant__ int c_O1[4] = {9,9,73,73};
__constant__ int c_O2[4] = {1,1,1,9};

__device__ __forceinline__ float2 cmul(float2 a, float2 b) {
    return make_float2(fmaf(a.x, b.x, -a.y * b.y), fmaf(a.x, b.y, a.y * b.x));
}
__device__ __forceinline__ void cmac(float2& acc, float ur, float ui, const float2 s) {
    acc.x = fmaf(ur, s.x, acc.x); acc.x = fmaf(-ui, s.y, acc.x);
    acc.y = fmaf(ur, s.y, acc.y); acc.y = fmaf(ui, s.x, acc.y);
}

// ===========================================================================
// Precompute: 80 blocks.
//  0..47  beamsplitter expm (64x64) -> phase-folded, block-packed
//  48..63 squeeze 8x8 expm  (l*4+w) -> pending intf1 phases folded into columns
//  64..79 displacement 8x8  (l*4+w) -> pending intf2 phases folded into columns
// Diagonal rotations/Kerr are folded as input-column phases of the next gate
// touching that mode. Pending phase per mode is alpha*n + beta*n^2.
// ===========================================================================
__global__ __launch_bounds__(NTHR) void precompute_kernel(
    const float* __restrict__ th1, const float* __restrict__ ph1,
    const float* __restrict__ th2, const float* __restrict__ ph2,
    const float* __restrict__ dr,  const float* __restrict__ dphi,
    const float* __restrict__ sr,  const float* __restrict__ sphi,
    const float* __restrict__ kerr)
{
    __shared__ float2 T[4096 + 128];
    int bid = blockIdx.x, t = threadIdx.x;

    if (bid < 48) {
        int l = bid / 12, rem = bid % 12, intf = rem / 6, p = rem % 6;
        int i = c_PI[p], j = c_PJ[p];
        const float* th = intf ? th2 : th1;
        const float* PH = (intf ? ph2 : ph1) + l * 16;
        float theta = th[l*16 + i*4 + j];
        float phiv  = PH[i*4 + j];
        float cp, sp; sincosf(phiv, &sp, &cp);
        const float scale = 1.0f / 256.0f;   // 8 squarings

        for (int e = t; e < 4096; e += NTHR) {
            int r = e >> 6, c = e & 63;
            T[e] = make_float2((r == c) ? 1.f : 0.f, 0.f);
        }
        __syncthreads();

        // Taylor Horner with sparse H (2 nonzeros per row), K=10
        for (int k = 10; k >= 1; k--) {
            float invk = 1.0f / (float)k;
            float2 Cn[16];
            #pragma unroll
            for (int q = 0; q < 16; q++) {
                int e = t * 16 + q;
                int r = e >> 6, c = e & 63;
                int a = r >> 3, b = r & 7;
                float2 acc = make_float2(0.f, 0.f);
                if (a < 7 && b > 0) {
                    float coef = theta * sqrtf((float)((a + 1) * b)) * scale;
                    float2 co = make_float2(coef * cp, coef * sp);
                    float2 pr = cmul(co, T[((a + 1) * 8 + (b - 1)) * 64 + c]);
                    acc.x += pr.x; acc.y += pr.y;
                }
                if (a > 0 && b < 7) {
                    float coef = theta * sqrtf((float)(a * (b + 1))) * scale;
                    float2 co = make_float2(-coef * cp, coef * sp);
                    float2 pr = cmul(co, T[((a - 1) * 8 + (b + 1)) * 64 + c]);
                    acc.x += pr.x; acc.y += pr.y;
                }
                acc.x *= invk; acc.y *= invk;
                if (r == c) acc.x += 1.0f;
                Cn[q] = acc;
            }
            __syncthreads();
            #pragma unroll
            for (int q = 0; q < 16; q++) T[t * 16 + q] = Cn[q];
            __syncthreads();
        }
        // 8 dense squarings
        for (int sq = 0; sq < 8; sq++) {
            float2 Cn[16];
            #pragma unroll
            for (int q = 0; q < 16; q++) {
                int e = t * 16 + q;
                int r = e >> 6, c = e & 63;
                float2 acc = make_float2(0.f, 0.f);
                for (int m = 0; m < 64; m++) {
                    float2 av = T[r * 64 + m];
                    float2 bv = T[m * 64 + c];
                    acc.x = fmaf(av.x, bv.x, acc.x); acc.x = fmaf(-av.y, bv.y, acc.x);
                    acc.y = fmaf(av.x, bv.y, acc.y); acc.y = fmaf(av.y, bv.x, acc.y);
                }
                Cn[q] = acc;
            }
            __syncthreads();
            #pragma unroll
            for (int q = 0; q < 16; q++) T[t * 16 + q] = Cn[q];
            __syncthreads();
        }

        // pending-phase simulation up to (but excluding) this BS
        float a4[4] = {PH[0], PH[5], PH[10], PH[15]};
        float b4[4] = {0.f, 0.f, 0.f, 0.f};
        if (intf == 0 && l > 0) {
            b4[0] = kerr[(l-1)*4+0]; b4[1] = kerr[(l-1)*4+1];
            b4[2] = kerr[(l-1)*4+2]; b4[3] = kerr[(l-1)*4+3];
        }
        for (int pp = 0; pp < p; pp++) {
            int ii = c_PI[pp], jj = c_PJ[pp];
            a4[ii] = 0.f; b4[ii] = 0.f;
            a4[jj] = PH[jj*4 + ii]; b4[jj] = 0.f;
        }
        float Ai = a4[i], Bi = b4[i], Aj = a4[j], Bj = b4[j];

        // pack (with input-phase fold) into padded block layout
        for (int e2 = t; e2 < 376; e2 += NTHR) {
            int n = 0;
            #pragma unroll
            for (int m = 1; m < 15; m++) if (e2 >= OFFP[m]) n = m;
            int K = 8 - ((n < 7) ? (7 - n) : (n - 7));
            int RK = K + (K & 1);
            int lo = (n > 7) ? (n - 7) : 0;
            int loc = e2 - OFFP[n];
            int aidx = loc / RK, cidx = loc % RK;
            float2 v = make_float2(0.f, 0.f);
            if (cidx < K) {
                int a = lo + aidx, b = n - a, c = lo + cidx, d = n - c;
                v = T[(a * 8 + b) * 64 + (c * 8 + d)];
                float P = Ai * (float)c + Bi * (float)(c * c)
                        + Aj * (float)d + Bj * (float)(d * d);
                float sn, cn; sincosf(P, &sn, &cn);
                v = cmul(v, make_float2(cn, sn));
            }
            g_bs[bid][e2] = v;
        }
    } else {
        int idx = bid - 48;
        bool is_sq = (idx < 16);
        int li = is_sq ? idx : (idx - 16);
        int l2 = li >> 2, w = li & 3;
        float2* Tsm = T;
        float2* Hsm = T + 64;
        int r = t >> 3, c = t & 7;

        if (t < 64) {
            float2 h = make_float2(0.f, 0.f);
            if (is_sq) {
                float rv = sr[li], pv = sphi[li];
                float cps, sps; sincosf(pv, &sps, &cps);
                float zr = rv * cps, zi = rv * sps;
                if (c == r + 2) {
                    float f = sqrtf((float)((r + 1) * (r + 2)));
                    h.x += 0.5f * zr * f;  h.y += -0.5f * zi * f;
                }
                if (c + 2 == r) {
                    float f = sqrtf((float)((c + 1) * (c + 2)));
                    h.x += -0.5f * zr * f; h.y += -0.5f * zi * f;
                }
            } else {
                float rv = dr[li], pv = dphi[li];
                float mm = rv * cosf(pv);
                float thp = rv * sinf(pv);
                float cth, sth; sincosf(thp, &sth, &cth);
                float ax = mm * cth, ay = mm * sth;
                if (c + 1 == r) {
                    float f = sqrtf((float)r);
                    h.x += ax * f; h.y += ay * f;
                }
                if (c == r + 1) {
                    float f = sqrtf((float)(r + 1));
                    h.x += -ax * f; h.y += ay * f;
                }
            }
            const float sc16 = 1.0f / 16.0f;  // 4 squarings
            h.x *= sc16; h.y *= sc16;
            Hsm[t] = h;
            Tsm[t] = make_float2((r == c) ? 1.f : 0.f, 0.f);
        }
        __syncthreads();

        for (int k = 10; k >= 1; k--) {
            float2 v = make_float2(0.f, 0.f);
            if (t < 64) {
                #pragma unroll
                for (int m = 0; m < 8; m++) {
                    float2 hm = Hsm[r * 8 + m];
                    float2 tm = Tsm[m * 8 + c];
                    v.x = fmaf(hm.x, tm.x, v.x); v.x = fmaf(-hm.y, tm.y, v.x);
                    v.y = fmaf(hm.x, tm.y, v.y); v.y = fmaf(hm.y, tm.x, v.y);
                }
                float ik = 1.0f / (float)k;
                v.x *= ik; v.y *= ik;
                if (r == c) v.x += 1.0f;
            }
            __syncthreads();
            if (t < 64) Tsm[t] = v;
            __syncthreads();
        }
        for (int sq = 0; sq < 4; sq++) {
            float2 v = make_float2(0.f, 0.f);
            if (t < 64) {
                #pragma unroll
                for (int m = 0; m < 8; m++) {
                    float2 av = Tsm[r * 8 + m];
                    float2 bv = Tsm[m * 8 + c];
                    v.x = fmaf(av.x, bv.x, v.x); v.x = fmaf(-av.y, bv.y, v.x);
                    v.y = fmaf(av.x, bv.y, v.y); v.y = fmaf(av.y, bv.x, v.y);
                }
            }
            __syncthreads();
            if (t < 64) Tsm[t] = v;
            __syncthreads();
        }
        if (t < 64) {
            // fold pending interferometer phase into input column c
            const float* PH = (is_sq ? ph1 : ph2) + l2 * 16;
            float a4[4] = {PH[0], PH[5], PH[10], PH[15]};
            float b4[4] = {0.f, 0.f, 0.f, 0.f};
            if (is_sq && l2 > 0) {
                b4[0] = kerr[(l2-1)*4+0]; b4[1] = kerr[(l2-1)*4+1];
                b4[2] = kerr[(l2-1)*4+2]; b4[3] = kerr[(l2-1)*4+3];
            }
            for (int pp = 0; pp < 6; pp++) {
                int ii = c_PI[pp], jj = c_PJ[pp];
                a4[ii] = 0.f; b4[ii] = 0.f;
                a4[jj] = PH[jj*4 + ii]; b4[jj] = 0.f;
            }
            float P = a4[w] * (float)c + b4[w] * (float)(c * c);
            float sn, cn; sincosf(P, &sn, &cn);
            float2 v = cmul(Tsm[t], make_float2(cn, sn));
            if (is_sq) g_sq[li][t] = v;
            else       g_dp[li][t] = v;
        }
    }
}

// ===========================================================================
// Main kernel pieces (dynamic smem: [state | enc | red]); in-place state.
// ===========================================================================

// One photon-number block of a BS gate: K x K complex GEMV on one fiber.
// In place: all K inputs cached in registers before outputs are written.
template<int K>
__device__ __noinline__ void bs_block(const float4* __restrict__ U4,
                                      int base2, int dS)
{
    extern __shared__ float2 sm[];
    constexpr int R4 = (K + 1) / 2;   // float4 per padded row
    float2 inv[K];
    #pragma unroll
    for (int ci = 0; ci < K; ci++) inv[ci] = sm[base2 + ci * dS];
    #pragma unroll
    for (int ai = 0; ai < K; ai++) {
        float2 acc = make_float2(0.f, 0.f);
        #pragma unroll
        for (int q = 0; q < R4; q++) {
            float4 u = __ldg(U4 + ai * R4 + q);
            cmac(acc, u.x, u.y, inv[2 * q]);
            if (2 * q + 1 < K) cmac(acc, u.z, u.w, inv[2 * q + 1]);
        }
        sm[base2 + ai * dS] = acc;
    }
}

// Single-mode 8x8 gate, in place; 2 fibers per thread sharing matrix loads.
__device__ __noinline__ void apply1g(const float4* __restrict__ U4,
                                     int SM, int O0, int O1, int O2, int t)
{
    extern __shared__ float2 sm[];
    int r1 = t + NTHR;
    int ba = (t  >> 6) * O0 + ((t  >> 3) & 7) * O1 + (t  & 7) * O2;
    int bb = (r1 >> 6) * O0 + ((r1 >> 3) & 7) * O1 + (r1 & 7) * O2;
    float2 sva[8], svb[8];
    #pragma unroll
    for (int i = 0; i < 8; i++) { sva[i] = sm[ba + i * SM]; svb[i] = sm[bb + i * SM]; }
    #pragma unroll
    for (int o = 0; o < 8; o++) {
        float2 aa = make_float2(0.f, 0.f), ab = make_float2(0.f, 0.f);
        #pragma unroll
        for (int q = 0; q < 4; q++) {
            float4 u = __ldg(U4 + o * 4 + q);
            cmac(aa, u.x, u.y, sva[2 * q]); cmac(aa, u.z, u.w, sva[2 * q + 1]);
            cmac(ab, u.x, u.y, svb[2 * q]); cmac(ab, u.z, u.w, svb[2 * q + 1]);
        }
        sm[ba + o * SM] = aa; sm[bb + o * SM] = ab;
    }
}

// ===========================================================================
// Main kernel: one CTA per batch element, in-place state, 1 barrier/gate.
// ===========================================================================
__global__ __launch_bounds__(NTHR, 3) void qnn_main(
    const float* __restrict__ x, float* __restrict__ out)
{
    extern __shared__ float2 sm[];
    float* enc = (float*)(sm + ST_SIZE);   // encH[256] encA[256] encB[256] red[32]
    float* encH = enc, *encA = enc + 256, *encB = enc + 512;
    float* red = enc + 768;

    int b = blockIdx.x, t = threadIdx.x;

    // ---- per-sample encoding expm: E_g = expm(x_g (AD - A)), real 8x8 ----
    {
        int g = t >> 6, e = t & 63, r = e >> 3, c = e & 7;
        float xv = __ldg(&x[b * 4 + g]);
        float sc = xv * (1.0f / 64.0f);   // 6 squarings
        float h = 0.f;
        if (c == r - 1) h = sc * sqrtf((float)r);
        else if (c == r + 1) h = -sc * sqrtf((float)(r + 1));
        encH[g * 64 + e] = h;
        encA[g * 64 + e] = (r == c) ? 1.f : 0.f;
        __syncthreads();

        float* Ta = encA + g * 64;
        float* Tb = encB + g * 64;
        for (int k = 9; k >= 1; k--) {
            float acc = 0.f;
            #pragma unroll
            for (int m = 0; m < 8; m++)
                acc = fmaf(encH[g * 64 + r * 8 + m], Ta[m * 8 + c], acc);
            float v = acc / (float)k + ((r == c) ? 1.f : 0.f);
            Tb[e] = v;
            __syncthreads();
            float* tmp = Ta; Ta = Tb; Tb = tmp;
        }
        for (int sq = 0; sq < 6; sq++) {
            float acc = 0.f;
            #pragma unroll
            for (int m = 0; m < 8; m++) acc = fmaf(Ta[r * 8 + m], Ta[m * 8 + c], acc);
            Tb[e] = acc;
            __syncthreads();
            float* tmp = Ta; Ta = Tb; Tb = tmp;
        }
        // 15 swaps from encA -> final matrix lives in encB region
    }

    // ---- init state: outer product of E_g column 0 (vacuum input) ----
    #pragma unroll 1
    for (int q = 0; q < 16; q++) {
        int e = t * 16 + q;
        int i = e >> 9, j = (e >> 6) & 7, k = (e >> 3) & 7, l2 = e & 7;
        float v = encB[0 * 64 + i * 8] * encB[1 * 64 + j * 8]
                * encB[2 * 64 + k * 8] * encB[3 * 64 + l2 * 8];
        sm[i * S0 + j * S1 + k * S2 + l2] = make_float2(v, 0.f);
    }
    __syncthreads();

    // ---- circuit: per layer: 6 BS, 4 squeeze, 6 BS, 4 disp (diagonals folded) ----
    int f = t & 63, og = t >> 6;

    #pragma unroll 1
    for (int l = 0; l < 4; l++) {
        #pragma unroll 1
        for (int hh = 0; hh < 2; hh++) {
            #pragma unroll 1
            for (int p = 0; p < 6; p++) {
                const float4* U4 = (const float4*)g_bs[l * 12 + hh * 6 + p];
                int SA = c_SA[p], SB = c_SB[p];
                int base = (f >> 3) * c_Q0[p] + (f & 7) * c_Q1[p];
                int dS = SA - SB;
                if (og == 0) {
                    bs_block<8>(U4 + 78,  base + 7 * SB, dS);          // n=7
                    bs_block<4>(U4 + 9,   base + 3 * SB, dS);          // n=3
                    bs_block<2>(U4 + 1,   base + 1 * SB, dS);          // n=1
                    bs_block<1>(U4 + 0,   base,           dS);         // n=0
                } else if (og == 1) {
                    bs_block<7>(U4 + 50,  base + 6 * SB, dS);          // n=6
                    bs_block<5>(U4 + 17,  base + 4 * SB, dS);          // n=4
                    bs_block<3>(U4 + 3,   base + 2 * SB, dS);          // n=2
                    bs_block<2>(U4 + 185, base + 6 * SA + 7 * SB, dS); // n=13
                } else if (og == 2) {
                    bs_block<7>(U4 + 110, base + 1 * SA + 7 * SB, dS); // n=8
                    bs_block<5>(U4 + 156, base + 3 * SA + 7 * SB, dS); // n=10
                    bs_block<3>(U4 + 179, base + 5 * SA + 7 * SB, dS); // n=12
                    bs_block<1>(U4 + 187, base + 7 * SA + 7 * SB, dS); // n=14
                } else {
                    bs_block<6>(U4 + 32,  base + 5 * SB, dS);          // n=5
                    bs_block<6>(U4 + 138, base + 2 * SA + 7 * SB, dS); // n=9
                    bs_block<4>(U4 + 171, base + 4 * SA + 7 * SB, dS); // n=11
                }
                __syncthreads();
            }
            #pragma unroll 1
            for (int w = 0; w < 4; w++) {
                const float2* G = hh ? g_dp[l * 4 + w] : g_sq[l * 4 + w];
                apply1g((const float4*)G, c_SM[w], c_O0[w], c_O1[w], c_O2[w], t);
                __syncthreads();
            }
        }
    }

    // ---- expectations <n_w> ----
    float ev0 = 0.f, ev1 = 0.f, ev2 = 0.f, ev3 = 0.f;
    #pragma unroll 1
    for (int q = 0; q < 16; q++) {
        int e = t * 16 + q;
        int i = e >> 9, j = (e >> 6) & 7, k = (e >> 3) & 7, l2 = e & 7;
        float2 a = sm[i * S0 + j * S1 + k * S2 + l2];
        float p = a.x * a.x + a.y * a.y;
        ev0 = fmaf(p, (float)i, ev0);
        ev1 = fmaf(p, (float)j, ev1);
        ev2 = fmaf(p, (float)k, ev2);
        ev3 = fmaf(p, (float)l2, ev3);
    }
    #pragma unroll
    for (int off2 = 16; off2; off2 >>= 1) {
        ev0 += __shfl_down_sync(0xFFFFFFFFu, ev0, off2);
        ev1 += __shfl_down_sync(0xFFFFFFFFu, ev1, off2);
        ev2 += __shfl_down_sync(0xFFFFFFFFu, ev2, off2);
        ev3 += __shfl_down_sync(0xFFFFFFFFu, ev3, off2);
    }
    int wid = t >> 5, lid = t & 31;
    if (lid == 0) {
        red[0 * 8 + wid] = ev0; red[1 * 8 + wid] = ev1;
        red[2 * 8 + wid] = ev2; red[3 * 8 + wid] = ev3;
    }
    __syncthreads();
    if (t < 4) {
        float s = 0.f;
        #pragma unroll
        for (int wv = 0; wv < 8; wv++) s += red[t * 8 + wv];
        out[b * 4 + t] = s;
    }
}

extern "C" void kernel_launch(void* const* d_in, const int* in_sizes, int n_in,
                              void* d_out, int out_size) {
    const float* x    = (const float*)d_in[0];
    const float* th1  = (const float*)d_in[1];
    const float* ph1  = (const float*)d_in[2];
    const float* th2  = (const float*)d_in[3];
    const float* ph2  = (const float*)d_in[4];
    const float* dr   = (const float*)d_in[5];
    const float* dphi = (const float*)d_in[6];
    const float* sr   = (const float*)d_in[7];
    const float* sphi = (const float*)d_in[8];
    const float* kerr = (const float*)d_in[9];
    float* out = (float*)d_out;
    int Bn = in_sizes[0] / 4;

    // dynamic smem: 1 state buffer + enc scratch + reduction
    int smem_bytes = ST_SIZE * (int)sizeof(float2) + (768 + 32) * (int)sizeof(float);
    cudaFuncSetAttribute(qnn_main, cudaFuncAttributeMaxDynamicSharedMemorySize, smem_bytes);

    precompute_kernel<<<80, NTHR>>>(th1, ph1, th2, ph2, dr, dphi, sr, sphi, kerr);
    qnn_main<<<Bn, NTHR, smem_bytes>>>(x, out);
}

// round 8
// speedup vs baseline: 2.6467x; 1.0883x over previous
#include <cuda_runtime.h>
#include <cuda_bf16.h>

#define NTHR 256
// smem strides (float2 units) for the 4 mode axes; residues mod 16 = (8,5,11,1)
// chosen so every gate's 16-lane phase can be bank-conflict-free where possible.
#define S0 680
#define S1 85
#define S2 11
#define ST_SIZE 5440       // 7*680+7*85+7*11+7+1

// ---------------------------------------------------------------------------
// Packed block-diagonal beamsplitter storage (two complex entries per float4).
// Block n (total photon number 0..14): K = 8-|n-7| rows/cols, row padded to
// RK = K+(K&1) float2 so every row is float4-aligned.
// ---------------------------------------------------------------------------
__device__ __align__(16) float2 g_bs[48][376];
__device__ __align__(16) float2 g_sq[16][64];   // squeeze  [out*8+in], phases folded
__device__ __align__(16) float2 g_dp[16][64];   // displacement, phases folded

__constant__ int OFFP[16] = {0,2,6,18,34,64,100,156,220,276,312,342,358,370,374,376};
__constant__ int c_PI[6] = {0,0,0,1,1,2};
__constant__ int c_PJ[6] = {1,2,3,2,3,3};
// BS strides per pair p: active modes (i,j) and spectators (f>>3 axis, f&7 axis)
// mode strides: m0=680, m1=85, m2=11, m3=1
__constant__ int c_SA[6] = {680,680,680,85,85,11};
__constant__ int c_SB[6] = {85,11,1,11,1,1};
__constant__ int c_Q0[6] = {11,85,85,680,680,680};  // f>>3 axis (mode0 for p>=3: conflict-free)
__constant__ int c_Q1[6] = {1,1,11,1,11,85};        // f&7 axis (odd stride)
// single-mode gate fiber maps: base = (t&7)*B0 + ((t>>3)&7)*B1 + (t>>6)*B2,
// second fiber = base + P.  Mode-0 (even stride 680) on bits 3-5 for w=1,2,3.
__constant__ int c1g_SM[4] = {680,85,11,1};
__constant__ int c1g_B0[4] = {1,11,85,11};
__constant__ int c1g_B1[4] = {85,680,680,680};
__constant__ int c1g_B2[4] = {11,1,1,85};
__constant__ int c1g_P[4]  = {44,4,4,340};

__device__ __forceinline__ float2 cmul(float2 a, float2 b) {
    return make_float2(fmaf(a.x, b.x, -a.y * b.y), fmaf(a.x, b.y, a.y * b.x));
}
__device__ __forceinline__ void cmac(float2& acc, float ur, float ui, const float2 s) {
    acc.x = fmaf(ur, s.x, acc.x); acc.x = fmaf(-ui, s.y, acc.x);
    acc.y = fmaf(ur, s.y, acc.y); acc.y = fmaf(ui, s.x, acc.y);
}

// ===========================================================================
// Precompute: 80 blocks (unchanged from R6).
// ===========================================================================
__global__ __launch_bounds__(NTHR) void precompute_kernel(
    const float* __restrict__ th1, const float* __restrict__ ph1,
    const float* __restrict__ th2, const float* __restrict__ ph2,
    const float* __restrict__ dr,  const float* __restrict__ dphi,
    const float* __restrict__ sr,  const float* __restrict__ sphi,
    const float* __restrict__ kerr)
{
    __shared__ float2 T[4096 + 128];
    int bid = blockIdx.x, t = threadIdx.x;

    if (bid < 48) {
        int l = bid / 12, rem = bid % 12, intf = rem / 6, p = rem % 6;
        int i = c_PI[p], j = c_PJ[p];
        const float* th = intf ? th2 : th1;
        const float* PH = (intf ? ph2 : ph1) + l * 16;
        float theta = th[l*16 + i*4 + j];
        float phiv  = PH[i*4 + j];
        float cp, sp; sincosf(phiv, &sp, &cp);
        const float scale = 1.0f / 256.0f;   // 8 squarings

        for (int e = t; e < 4096; e += NTHR) {
            int r = e >> 6, c = e & 63;
            T[e] = make_float2((r == c) ? 1.f : 0.f, 0.f);
        }
        __syncthreads();

        for (int k = 10; k >= 1; k--) {
            float invk = 1.0f / (float)k;
            float2 Cn[16];
            #pragma unroll
            for (int q = 0; q < 16; q++) {
                int e = t * 16 + q;
                int r = e >> 6, c = e & 63;
                int a = r >> 3, b = r & 7;
                float2 acc = make_float2(0.f, 0.f);
                if (a < 7 && b > 0) {
                    float coef = theta * sqrtf((float)((a + 1) * b)) * scale;
                    float2 co = make_float2(coef * cp, coef * sp);
                    float2 pr = cmul(co, T[((a + 1) * 8 + (b - 1)) * 64 + c]);
                    acc.x += pr.x; acc.y += pr.y;
                }
                if (a > 0 && b < 7) {
                    float coef = theta * sqrtf((float)(a * (b + 1))) * scale;
                    float2 co = make_float2(-coef * cp, coef * sp);
                    float2 pr = cmul(co, T[((a - 1) * 8 + (b + 1)) * 64 + c]);
                    acc.x += pr.x; acc.y += pr.y;
                }
                acc.x *= invk; acc.y *= invk;
                if (r == c) acc.x += 1.0f;
                Cn[q] = acc;
            }
            __syncthreads();
            #pragma unroll
            for (int q = 0; q < 16; q++) T[t * 16 + q] = Cn[q];
            __syncthreads();
        }
        for (int sq = 0; sq < 8; sq++) {
            float2 Cn[16];
            #pragma unroll
            for (int q = 0; q < 16; q++) {
                int e = t * 16 + q;
                int r = e >> 6, c = e & 63;
                float2 acc = make_float2(0.f, 0.f);
                for (int m = 0; m < 64; m++) {
                    float2 av = T[r * 64 + m];
                    float2 bv = T[m * 64 + c];
                    acc.x = fmaf(av.x, bv.x, acc.x); acc.x = fmaf(-av.y, bv.y, acc.x);
                    acc.y = fmaf(av.x, bv.y, acc.y); acc.y = fmaf(av.y, bv.x, acc.y);
                }
                Cn[q] = acc;
            }
            __syncthreads();
            #pragma unroll
            for (int q = 0; q < 16; q++) T[t * 16 + q] = Cn[q];
            __syncthreads();
        }

        float a4[4] = {PH[0], PH[5], PH[10], PH[15]};
        float b4[4] = {0.f, 0.f, 0.f, 0.f};
        if (intf == 0 && l > 0) {
            b4[0] = kerr[(l-1)*4+0]; b4[1] = kerr[(l-1)*4+1];
            b4[2] = kerr[(l-1)*4+2]; b4[3] = kerr[(l-1)*4+3];
        }
        for (int pp = 0; pp < p; pp++) {
            int ii = c_PI[pp], jj = c_PJ[pp];
            a4[ii] = 0.f; b4[ii] = 0.f;
            a4[jj] = PH[jj*4 + ii]; b4[jj] = 0.f;
        }
        float Ai = a4[i], Bi = b4[i], Aj = a4[j], Bj = b4[j];

        for (int e2 = t; e2 < 376; e2 += NTHR) {
            int n = 0;
            #pragma unroll
            for (int m = 1; m < 15; m++) if (e2 >= OFFP[m]) n = m;
            int K = 8 - ((n < 7) ? (7 - n) : (n - 7));
            int RK = K + (K & 1);
            int lo = (n > 7) ? (n - 7) : 0;
            int loc = e2 - OFFP[n];
            int aidx = loc / RK, cidx = loc % RK;
            float2 v = make_float2(0.f, 0.f);
            if (cidx < K) {
                int a = lo + aidx, b = n - a, c = lo + cidx, d = n - c;
                v = T[(a * 8 + b) * 64 + (c * 8 + d)];
                float P = Ai * (float)c + Bi * (float)(c * c)
                        + Aj * (float)d + Bj * (float)(d * d);
                float sn, cn; sincosf(P, &sn, &cn);
                v = cmul(v, make_float2(cn, sn));
            }
            g_bs[bid][e2] = v;
        }
    } else {
        int idx = bid - 48;
        bool is_sq = (idx < 16);
        int li = is_sq ? idx : (idx - 16);
        int l2 = li >> 2, w = li & 3;
        float2* Tsm = T;
        float2* Hsm = T + 64;
        int r = t >> 3, c = t & 7;

        if (t < 64) {
            float2 h = make_float2(0.f, 0.f);
            if (is_sq) {
                float rv = sr[li], pv = sphi[li];
                float cps, sps; sincosf(pv, &sps, &cps);
                float zr = rv * cps, zi = rv * sps;
                if (c == r + 2) {
                    float f = sqrtf((float)((r + 1) * (r + 2)));
                    h.x += 0.5f * zr * f;  h.y += -0.5f * zi * f;
                }
                if (c + 2 == r) {
                    float f = sqrtf((float)((c + 1) * (c + 2)));
                    h.x += -0.5f * zr * f; h.y += -0.5f * zi * f;
                }
            } else {
                float rv = dr[li], pv = dphi[li];
                float mm = rv * cosf(pv);
                float thp = rv * sinf(pv);
                float cth, sth; sincosf(thp, &sth, &cth);
                float ax = mm * cth, ay = mm * sth;
                if (c + 1 == r) {
                    float f = sqrtf((float)r);
                    h.x += ax * f; h.y += ay * f;
                }
                if (c == r + 1) {
                    float f = sqrtf((float)(r + 1));
                    h.x += -ax * f; h.y += ay * f;
                }
            }
            const float sc16 = 1.0f / 16.0f;  // 4 squarings
            h.x *= sc16; h.y *= sc16;
            Hsm[t] = h;
            Tsm[t] = make_float2((r == c) ? 1.f : 0.f, 0.f);
        }
        __syncthreads();

        for (int k = 10; k >= 1; k--) {
            float2 v = make_float2(0.f, 0.f);
            if (t < 64) {
                #pragma unroll
                for (int m = 0; m < 8; m++) {
                    float2 hm = Hsm[r * 8 + m];
                    float2 tm = Tsm[m * 8 + c];
                    v.x = fmaf(hm.x, tm.x, v.x); v.x = fmaf(-hm.y, tm.y, v.x);
                    v.y = fmaf(hm.x, tm.y, v.y); v.y = fmaf(hm.y, tm.x, v.y);
                }
                float ik = 1.0f / (float)k;
                v.x *= ik; v.y *= ik;
                if (r == c) v.x += 1.0f;
            }
            __syncthreads();
            if (t < 64) Tsm[t] = v;
            __syncthreads();
        }
        for (int sq = 0; sq < 4; sq++) {
            float2 v = make_float2(0.f, 0.f);
            if (t < 64) {
                #pragma unroll
                for (int m = 0; m < 8; m++) {
                    float2 av = Tsm[r * 8 + m];
                    float2 bv = Tsm[m * 8 + c];
                    v.x = fmaf(av.x, bv.x, v.x); v.x = fmaf(-av.y, bv.y, v.x);
                    v.y = fmaf(av.x, bv.y, v.y); v.y = fmaf(av.y, bv.x, v.y);
                }
            }
            __syncthreads();
            if (t < 64) Tsm[t] = v;
            __syncthreads();
        }
        if (t < 64) {
            const float* PH = (is_sq ? ph1 : ph2) + l2 * 16;
            float a4[4] = {PH[0], PH[5], PH[10], PH[15]};
            float b4[4] = {0.f, 0.f, 0.f, 0.f};
            if (is_sq && l2 > 0) {
                b4[0] = kerr[(l2-1)*4+0]; b4[1] = kerr[(l2-1)*4+1];
                b4[2] = kerr[(l2-1)*4+2]; b4[3] = kerr[(l2-1)*4+3];
            }
            for (int pp = 0; pp < 6; pp++) {
                int ii = c_PI[pp], jj = c_PJ[pp];
                a4[ii] = 0.f; b4[ii] = 0.f;
                a4[jj] = PH[jj*4 + ii]; b4[jj] = 0.f;
            }
            float P = a4[w] * (float)c + b4[w] * (float)(c * c);
            float sn, cn; sincosf(P, &sn, &cn);
            float2 v = cmul(Tsm[t], make_float2(cn, sn));
            if (is_sq) g_sq[li][t] = v;
            else       g_dp[li][t] = v;
        }
    }
}

// ===========================================================================
// Main kernel pieces (dynamic smem: [state | enc | red]); in-place state.
// ===========================================================================

template<int K>
__device__ __noinline__ void bs_block(const float4* __restrict__ U4,
                                      int base2, int dS)
{
    extern __shared__ float2 sm[];
    constexpr int R4 = (K + 1) / 2;
    float2 inv[K];
    #pragma unroll
    for (int ci = 0; ci < K; ci++) inv[ci] = sm[base2 + ci * dS];
    #pragma unroll
    for (int ai = 0; ai < K; ai++) {
        float2 acc = make_float2(0.f, 0.f);
        #pragma unroll
        for (int q = 0; q < R4; q++) {
            float4 u = __ldg(U4 + ai * R4 + q);
            cmac(acc, u.x, u.y, inv[2 * q]);
            if (2 * q + 1 < K) cmac(acc, u.z, u.w, inv[2 * q + 1]);
        }
        sm[base2 + ai * dS] = acc;
    }
}

// Single-mode 8x8 gate, in place; 2 fibers per thread sharing matrix loads.
// Fiber map: base = (t&7)*B0 + ((t>>3)&7)*B1 + (t>>6)*B2, fiber2 = +P.
__device__ __noinline__ void apply1g(const float4* __restrict__ U4,
                                     int SM, int B0, int B1, int B2, int P, int t)
{
    extern __shared__ float2 sm[];
    int ba = (t & 7) * B0 + ((t >> 3) & 7) * B1 + (t >> 6) * B2;
    int bb = ba + P;
    float2 sva[8], svb[8];
    #pragma unroll
    for (int i = 0; i < 8; i++) { sva[i] = sm[ba + i * SM]; svb[i] = sm[bb + i * SM]; }
    #pragma unroll
    for (int o = 0; o < 8; o++) {
        float2 aa = make_float2(0.f, 0.f), ab = make_float2(0.f, 0.f);
        #pragma unroll
        for (int q = 0; q < 4; q++) {
            float4 u = __ldg(U4 + o * 4 + q);
            cmac(aa, u.x, u.y, sva[2 * q]); cmac(aa, u.z, u.w, sva[2 * q + 1]);
            cmac(ab, u.x, u.y, svb[2 * q]); cmac(ab, u.z, u.w, svb[2 * q + 1]);
        }
        sm[ba + o * SM] = aa; sm[bb + o * SM] = ab;
    }
}

// ===========================================================================
// Main kernel: one CTA per batch element, in-place state, 1 barrier/gate.
// ===========================================================================
__global__ __launch_bounds__(NTHR, 3) void qnn_main(
    const float* __restrict__ x, float* __restrict__ out)
{
    extern __shared__ float2 sm[];
    float* enc = (float*)(sm + ST_SIZE);   // encH[256] encA[256] encB[256] red[32]
    float* encH = enc, *encA = enc + 256, *encB = enc + 512;
    float* red = enc + 768;

    int b = blockIdx.x, t = threadIdx.x;

    // ---- per-sample encoding expm: E_g = expm(x_g (AD - A)), real 8x8 ----
    {
        int g = t >> 6, e = t & 63, r = e >> 3, c = e & 7;
        float xv = __ldg(&x[b * 4 + g]);
        float sc = xv * (1.0f / 64.0f);   // 6 squarings
        float h = 0.f;
        if (c == r - 1) h = sc * sqrtf((float)r);
        else if (c == r + 1) h = -sc * sqrtf((float)(r + 1));
        encH[g * 64 + e] = h;
        encA[g * 64 + e] = (r == c) ? 1.f : 0.f;
        __syncthreads();

        float* Ta = encA + g * 64;
        float* Tb = encB + g * 64;
        for (int k = 9; k >= 1; k--) {
            float acc = 0.f;
            #pragma unroll
            for (int m = 0; m < 8; m++)
                acc = fmaf(encH[g * 64 + r * 8 + m], Ta[m * 8 + c], acc);
            float v = acc / (float)k + ((r == c) ? 1.f : 0.f);
            Tb[e] = v;
            __syncthreads();
            float* tmp = Ta; Ta = Tb; Tb = tmp;
        }
        for (int sq = 0; sq < 6; sq++) {
            float acc = 0.f;
            #pragma unroll
            for (int m = 0; m < 8; m++) acc = fmaf(Ta[r * 8 + m], Ta[m * 8 + c], acc);
            Tb[e] = acc;
            __syncthreads();
            float* tmp = Ta; Ta = Tb; Tb = tmp;
        }
        // 15 swaps from encA -> final matrix lives in encB region
    }

    // ---- init state: outer product of E_g column 0 (vacuum input) ----
    #pragma unroll 1
    for (int q = 0; q < 16; q++) {
        int e = t * 16 + q;
        int i = e >> 9, j = (e >> 6) & 7, k = (e >> 3) & 7, l2 = e & 7;
        float v = encB[0 * 64 + i * 8] * encB[1 * 64 + j * 8]
                * encB[2 * 64 + k * 8] * encB[3 * 64 + l2 * 8];
        sm[i * S0 + j * S1 + k * S2 + l2] = make_float2(v, 0.f);
    }
    __syncthreads();

    // ---- circuit: per layer: 6 BS, 4 squeeze, 6 BS, 4 disp (diagonals folded) ----
    int f = t & 63, og = t >> 6;

    #pragma unroll 1
    for (int l = 0; l < 4; l++) {
        #pragma unroll 1
        for (int hh = 0; hh < 2; hh++) {
            #pragma unroll 1
            for (int p = 0; p < 6; p++) {
                const float4* U4 = (const float4*)g_bs[l * 12 + hh * 6 + p];
                int SA = c_SA[p], SB = c_SB[p];
                int base = (f >> 3) * c_Q0[p] + (f & 7) * c_Q1[p];
                int dS = SA - SB;
                if (og == 0) {
                    bs_block<8>(U4 + 78,  base + 7 * SB, dS);          // n=7
                    bs_block<4>(U4 + 9,   base + 3 * SB, dS);          // n=3
                    bs_block<2>(U4 + 1,   base + 1 * SB, dS);          // n=1
                    bs_block<1>(U4 + 0,   base,           dS);         // n=0
                } else if (og == 1) {
                    bs_block<7>(U4 + 50,  base + 6 * SB, dS);          // n=6
                    bs_block<5>(U4 + 17,  base + 4 * SB, dS);          // n=4
                    bs_block<3>(U4 + 3,   base + 2 * SB, dS);          // n=2
                    bs_block<2>(U4 + 185, base + 6 * SA + 7 * SB, dS); // n=13
                } else if (og == 2) {
                    bs_block<7>(U4 + 110, base + 1 * SA + 7 * SB, dS); // n=8
                    bs_block<5>(U4 + 156, base + 3 * SA + 7 * SB, dS); // n=10
                    bs_block<3>(U4 + 179, base + 5 * SA + 7 * SB, dS); // n=12
                    bs_block<1>(U4 + 187, base + 7 * SA + 7 * SB, dS); // n=14
                } else {
                    bs_block<6>(U4 + 32,  base + 5 * SB, dS);          // n=5
                    bs_block<6>(U4 + 138, base + 2 * SA + 7 * SB, dS); // n=9
                    bs_block<4>(U4 + 171, base + 4 * SA + 7 * SB, dS); // n=11
                }
                __syncthreads();
            }
            #pragma unroll 1
            for (int w = 0; w < 4; w++) {
                const float2* G = hh ? g_dp[l * 4 + w] : g_sq[l * 4 + w];
                apply1g((const float4*)G, c1g_SM[w], c1g_B0[w], c1g_B1[w],
                        c1g_B2[w], c1g_P[w], t);
                __syncthreads();
            }
        }
    }

    // ---- expectations <n_w> ----
    float ev0 = 0.f, ev1 = 0.f, ev2 = 0.f, ev3 = 0.f;
    #pragma unroll 1
    for (int q = 0; q < 16; q++) {
        int e = t * 16 + q;
        int i = e >> 9, j = (e >> 6) & 7, k = (e >> 3) & 7, l2 = e & 7;
        float2 a = sm[i * S0 + j * S1 + k * S2 + l2];
        float p = a.x * a.x + a.y * a.y;
        ev0 = fmaf(p, (float)i, ev0);
        ev1 = fmaf(p, (float)j, ev1);
        ev2 = fmaf(p, (float)k, ev2);
        ev3 = fmaf(p, (float)l2, ev3);
    }
    #pragma unroll
    for (int off2 = 16; off2; off2 >>= 1) {
        ev0 += __shfl_down_sync(0xFFFFFFFFu, ev0, off2);
        ev1 += __shfl_down_sync(0xFFFFFFFFu, ev1, off2);
        ev2 += __shfl_down_sync(0xFFFFFFFFu, ev2, off2);
        ev3 += __shfl_down_sync(0xFFFFFFFFu, ev3, off2);
    }
    int wid = t >> 5, lid = t & 31;
    if (lid == 0) {
        red[0 * 8 + wid] = ev0; red[1 * 8 + wid] = ev1;
        red[2 * 8 + wid] = ev2; red[3 * 8 + wid] = ev3;
    }
    __syncthreads();
    if (t < 4) {
        float s = 0.f;
        #pragma unroll
        for (int wv = 0; wv < 8; wv++) s += red[t * 8 + wv];
        out[b * 4 + t] = s;
    }
}

extern "C" void kernel_launch(void* const* d_in, const int* in_sizes, int n_in,
                              void* d_out, int out_size) {
    const float* x    = (const float*)d_in[0];
    const float* th1  = (const float*)d_in[1];
    const float* ph1  = (const float*)d_in[2];
    const float* th2  = (const float*)d_in[3];
    const float* ph2  = (const float*)d_in[4];
    const float* dr   = (const float*)d_in[5];
    const float* dphi = (const float*)d_in[6];
    const float* sr   = (const float*)d_in[7];
    const float* sphi = (const float*)d_in[8];
    const float* kerr = (const float*)d_in[9];
    float* out = (float*)d_out;
    int Bn = in_sizes[0] / 4;

    int smem_bytes = ST_SIZE * (int)sizeof(float2) + (768 + 32) * (int)sizeof(float);
    cudaFuncSetAttribute(qnn_main, cudaFuncAttributeMaxDynamicSharedMemorySize, smem_bytes);

    precompute_kernel<<<80, NTHR>>>(th1, ph1, th2, ph2, dr, dphi, sr, sphi, kerr);
    qnn_main<<<Bn, NTHR, smem_bytes>>>(x, out);
}